// round 3
// baseline (speedup 1.0000x reference)
#include <cuda_runtime.h>

// Problem constants
#define NC 4
#define NB 128
#define NG 2048
#define NS 32
#define NL 3
#define NBQ 4                 // 128 b-lanes split into 4 groups of 32
#define GPB 64                // g per block in kernel A
#define NWARPS 8
#define GPW (GPB/NWARPS)      // g per warp
#define NTOT (NC*NB*NG)       // 1,048,576
#define BGTOT (NB*NG)         // 262,144 (= 2^18)

// Scratch (no allocation allowed -> device globals)
__device__ float d_Z[NTOT];          // valuation storage (bq layout)
__device__ float d_T[NTOT];          // clause_eval output  (bq layout)
__device__ float d_xq[BGTOT];        // transposed x (bq layout, shared by all c)
__device__ unsigned int d_slots[8];  // float-as-uint max accumulators

__device__ __forceinline__ float slot_scale(int idx) {
    if (idx < 0) return 1.0f;
    float m = __uint_as_float(d_slots[idx]);
    return (m > 1.0f) ? (1.0f / m) : 1.0f;
}

// Zero the max slots + build xq[(bq*NG+g)*32 + lane] = x[(bq*32+lane)*NG + g]
__global__ void init_kernel(const float* __restrict__ x) {
    int i = blockIdx.x * blockDim.x + threadIdx.x;
    if (i < 8) d_slots[i] = 0u;
    if (i < BGTOT) {
        int lane = i & 31;
        int g = (i >> 5) & (NG - 1);
        int bq = i >> 16;
        d_xq[i] = x[(bq * 32 + lane) * NG + g];
    }
}

// Kernel A: T[c,b,g] = gamma*logsumexp_s( prod_l R[c,b,I[c,g,s,l]] / gamma )
// R = src * scale(scaleIdx);  also atomicMax global max of T into slot maxIdx.
__global__ void __launch_bounds__(256) kernelA(const int* __restrict__ I,
                                               int srcIsZ, int scaleIdx, int maxIdx) {
    __shared__ int sIdx[GPB * NS * NL];   // 6144 ints = 24KB
    __shared__ float sMax[NWARPS];
    const int c = blockIdx.z, bq = blockIdx.y;
    const int g0 = blockIdx.x * GPB;
    const int tid = threadIdx.x, lane = tid & 31, w = tid >> 5;

    // Stage this block's index tile (coalesced) into shared
    const int* Ibase = I + (c * NG + g0) * (NS * NL);
    #pragma unroll 4
    for (int i = tid; i < GPB * NS * NL; i += 256) sIdx[i] = Ibase[i];
    __syncthreads();

    const float s = slot_scale(scaleIdx);
    const float s3 = s * s * s;                  // scale folded into 3-way product
    const float inv = s3 * 100.0f;               // (1/gamma) * s3
    const float* __restrict__ slab =
        srcIsZ ? (d_Z + (c * NBQ + bq) * (NG * 32)) : (d_xq + bq * (NG * 32));

    float wmax = 0.0f;
    #pragma unroll 1
    for (int gi = 0; gi < GPW; gi++) {
        const int gl = w * GPW + gi;
        const int* ip = sIdx + gl * (NS * NL);
        float p[NS];
        float amax = 0.0f;                        // products are >= 0
        #pragma unroll
        for (int ss = 0; ss < NS; ss++) {
            int i0 = ip[ss * 3 + 0];
            int i1 = ip[ss * 3 + 1];
            int i2 = ip[ss * 3 + 2];
            float v0 = slab[(i0 << 5) + lane];    // 128B warp-coalesced gather
            float v1 = slab[(i1 << 5) + lane];
            float v2 = slab[(i2 << 5) + lane];
            float pp = v0 * v1 * v2;
            p[ss] = pp;
            amax = fmaxf(amax, pp);
        }
        float sum = 0.0f;
        #pragma unroll
        for (int ss = 0; ss < NS; ss++)
            sum += __expf((p[ss] - amax) * inv);
        float t = fmaf(0.01f, __logf(sum), amax * s3);
        d_T[((c * NBQ + bq) * NG + g0 + gl) * 32 + lane] = t;
        wmax = fmaxf(wmax, t);
    }
    #pragma unroll
    for (int o = 16; o; o >>= 1) wmax = fmaxf(wmax, __shfl_xor_sync(0xffffffffu, wmax, o));
    if (lane == 0) sMax[w] = wmax;
    __syncthreads();
    if (tid == 0) {
        float bm = sMax[0];
        #pragma unroll
        for (int k = 1; k < NWARPS; k++) bm = fmaxf(bm, sMax[k]);
        atomicMax(&d_slots[maxIdx], __float_as_uint(bm));
    }
}

// Kernel B: Z = softor2(R, T') elementwise;  R = src*scale(rIdx), T' = T*scale(tIdx).
// atomicMax global max of Z into slot maxIdx.
__global__ void __launch_bounds__(256) kernelB(int srcIsZ, int rIdx, int tIdx, int maxIdx) {
    __shared__ float sMax[8];
    int i = blockIdx.x * 256 + threadIdx.x;
    const float sr = slot_scale(rIdx);
    const float st = slot_scale(tIdx);
    float r = (srcIsZ ? d_Z[i] : d_xq[i & (BGTOT - 1)]) * sr;
    float t = d_T[i] * st;
    float mx = fmaxf(r, t), mn = fminf(r, t);
    float z = fmaf(0.01f, __logf(1.0f + __expf((mn - mx) * 100.0f)), mx);
    d_Z[i] = z;

    float wm = z;
    #pragma unroll
    for (int o = 16; o; o >>= 1) wm = fmaxf(wm, __shfl_xor_sync(0xffffffffu, wm, o));
    int lane = threadIdx.x & 31, w = threadIdx.x >> 5;
    if (lane == 0) sMax[w] = wm;
    __syncthreads();
    if (threadIdx.x == 0) {
        float bm = sMax[0];
        #pragma unroll
        for (int k = 1; k < 8; k++) bm = fmaxf(bm, sMax[k]);
        atomicMax(&d_slots[maxIdx], __float_as_uint(bm));
    }
}

// Final: out[c,b,g] = Z[c,bq,g,lane] * scale(slot5), tiled transpose for coalescing.
__global__ void final_kernel(float* __restrict__ out) {
    __shared__ float tile[32][33];
    const int c = blockIdx.z, bq = blockIdx.y;
    const int g0 = blockIdx.x * 32;
    const int lane = threadIdx.x, ty = threadIdx.y;   // block (32, 8)
    const float sc = slot_scale(5);
    #pragma unroll
    for (int r = 0; r < 4; r++) {
        int gi = ty + r * 8;
        tile[gi][lane] = d_Z[((c * NBQ + bq) * NG + g0 + gi) * 32 + lane];
    }
    __syncthreads();
    #pragma unroll
    for (int r = 0; r < 4; r++) {
        int bl = ty + r * 8;
        out[(c * NB + bq * 32 + bl) * NG + g0 + lane] = tile[lane][bl] * sc;
    }
}

extern "C" void kernel_launch(void* const* d_in, const int* in_sizes, int n_in,
                              void* d_out, int out_size) {
    const float* x = (const float*)d_in[0];
    const int* I = (const int*)d_in[1];
    if (in_sizes[0] != BGTOT) {   // defensive: metadata order swap
        x = (const float*)d_in[1];
        I = (const int*)d_in[0];
    }
    float* out = (float*)d_out;

    init_kernel<<<(BGTOT + 255) / 256, 256>>>(x);

    dim3 gA(NG / GPB, NBQ, NC);          // 32 x 4 x 4 = 512 blocks
    dim3 gB(NTOT / 256);                 // 4096 blocks

    // step 0: R = x (broadcast over c)
    kernelA<<<gA, 256>>>(I, 0, -1, 0);
    kernelB<<<gB, 256>>>(0, -1, 0, 1);
    // step 1
    kernelA<<<gA, 256>>>(I, 1, 1, 2);
    kernelB<<<gB, 256>>>(1, 1, 2, 3);
    // step 2
    kernelA<<<gA, 256>>>(I, 1, 3, 4);
    kernelB<<<gB, 256>>>(1, 3, 4, 5);

    final_kernel<<<dim3(NG / 32, NBQ, NC), dim3(32, 8)>>>(out);
}